// round 1
// baseline (speedup 1.0000x reference)
#include <cuda_runtime.h>
#include <cuda_bf16.h>
#include <cstdint>

// Problem constants
#define B_   256
#define L_   512
#define E_   768
#define H_   384
#define NEXP 9

#define LEAKY 0.01f
#define LN_EPS 1e-5f

// Output layout (tuple order): output[B,2], rec_feature[B,E], bert_feature[B,E], domain_pred[B,N]
#define OUT_CLS_OFF  0
#define OUT_REC_OFF  (B_*2)                 // 512
#define OUT_BERT_OFF (B_*2 + B_*E_)         // 197120
#define OUT_DOM_OFF  (B_*2 + 2*B_*E_)       // 393728

// -------- device scratch (no allocations allowed) --------
#define NPART 2048            // B * 8 chunks
#define PART_STRIDE 772       // [0]=m, [1]=s, [4..772)=acc[768]
__device__ float g_partial[NPART * PART_STRIDE];
__device__ float g_pre_sh[B_ * H_];
__device__ float g_pre_sp[B_ * H_];
__device__ float g_feat[B_ * 2 * H_];       // [B,768]: shared | specific
__device__ float g_pre1[B_ * H_];
__device__ float g_rec[B_ * H_];
__device__ float g_pre2[B_ * E_];
__device__ float g_pre_d[B_ * H_];
__device__ float g_dom[B_ * H_];
__device__ int   g_perm[B_];
__device__ int   g_off[NEXP + 1];

__device__ __forceinline__ float warpAllSum(float v) {
    #pragma unroll
    for (int o = 16; o > 0; o >>= 1) v += __shfl_xor_sync(0xffffffffu, v, o);
    return v;
}

// ============================================================================
// Kernel 1: single-pass attention pooling, partial per (b, 64-row chunk).
// CTA = 256 threads = 8 warps; warp handles 8 rows of L. Online softmax.
// ============================================================================
__global__ void __launch_bounds__(256) pool_partial_k(
    const float* __restrict__ input, const float* __restrict__ w_att)
{
    int bx = blockIdx.x;
    int b = bx >> 3, chunk = bx & 7;
    int tid = threadIdx.x, lane = tid & 31, warp = tid >> 5;

    const float* base = input + ((size_t)(b * L_ + chunk * 64 + warp * 8)) * E_;

    float4 wr[6];
    #pragma unroll
    for (int k = 0; k < 6; k++)
        wr[k] = *(const float4*)(w_att + 4 * lane + 128 * k);

    float4 acc[6];
    #pragma unroll
    for (int k = 0; k < 6; k++) acc[k] = make_float4(0.f, 0.f, 0.f, 0.f);
    float m = -1e30f, s = 0.f;

    #pragma unroll
    for (int r = 0; r < 8; r++) {
        const float* row = base + (size_t)r * E_;
        float4 v[6];
        #pragma unroll
        for (int k = 0; k < 6; k++)
            v[k] = *(const float4*)(row + 4 * lane + 128 * k);

        float dot = 0.f;
        #pragma unroll
        for (int k = 0; k < 6; k++)
            dot += v[k].x * wr[k].x + v[k].y * wr[k].y + v[k].z * wr[k].z + v[k].w * wr[k].w;
        dot = warpAllSum(dot);

        float mn = fmaxf(m, dot);
        float sc = __expf(m - mn);     // exp(-inf)=0 on first row
        float w  = __expf(dot - mn);
        s = s * sc + w;
        #pragma unroll
        for (int k = 0; k < 6; k++) {
            acc[k].x = acc[k].x * sc + w * v[k].x;
            acc[k].y = acc[k].y * sc + w * v[k].y;
            acc[k].z = acc[k].z * sc + w * v[k].z;
            acc[k].w = acc[k].w * sc + w * v[k].w;
        }
        m = mn;
    }

    __shared__ float sm_m[8], sm_s[8];
    __shared__ float sm_acc[8][E_];
    __shared__ float sM, sc8[8];

    if (lane == 0) { sm_m[warp] = m; sm_s[warp] = s; }
    #pragma unroll
    for (int k = 0; k < 6; k++)
        *(float4*)&sm_acc[warp][4 * lane + 128 * k] = acc[k];
    __syncthreads();

    if (tid == 0) {
        float M = sm_m[0];
        #pragma unroll
        for (int w = 1; w < 8; w++) M = fmaxf(M, sm_m[w]);
        sM = M;
    }
    __syncthreads();
    if (tid < 8) sc8[tid] = __expf(sm_m[tid] - sM);
    __syncthreads();

    float* out = g_partial + (size_t)bx * PART_STRIDE;
    if (tid == 0) {
        float S = 0.f;
        #pragma unroll
        for (int w = 0; w < 8; w++) S += sc8[w] * sm_s[w];
        out[0] = sM; out[1] = S;
    }
    #pragma unroll
    for (int i = 0; i < 3; i++) {
        int e = tid + 256 * i;
        float t = 0.f;
        #pragma unroll
        for (int w = 0; w < 8; w++) t += sc8[w] * sm_acc[w][e];
        out[4 + e] = t;
    }
}

// Kernel 2: combine 8 chunk partials per b -> bert_feature (written to d_out)
__global__ void __launch_bounds__(256) pool_combine_k(float* __restrict__ bert)
{
    int b = blockIdx.x, tid = threadIdx.x;
    float mc[8];
    float M = -1e30f;
    #pragma unroll
    for (int c = 0; c < 8; c++) {
        mc[c] = g_partial[(size_t)(b * 8 + c) * PART_STRIDE];
        M = fmaxf(M, mc[c]);
    }
    float sc[8], S = 0.f;
    #pragma unroll
    for (int c = 0; c < 8; c++) {
        sc[c] = __expf(mc[c] - M);
        S += sc[c] * g_partial[(size_t)(b * 8 + c) * PART_STRIDE + 1];
    }
    float invS = 1.f / S;
    #pragma unroll
    for (int i = 0; i < 3; i++) {
        int e = tid + 256 * i;
        float t = 0.f;
        #pragma unroll
        for (int c = 0; c < 8; c++)
            t += sc[c] * g_partial[(size_t)(b * 8 + c) * PART_STRIDE + 4 + e];
        bert[(size_t)b * E_ + e] = t * invS;
    }
}

// ============================================================================
// Kernel 3: group sample indices by expert (for spec_W gather GEMM)
// ============================================================================
__global__ void perm_k(const int* __restrict__ D)
{
    __shared__ int cnt[NEXP];
    __shared__ int cur[NEXP];
    int tid = threadIdx.x;
    if (tid < NEXP) cnt[tid] = 0;
    __syncthreads();
    int n = D[tid];
    atomicAdd(&cnt[n], 1);
    __syncthreads();
    if (tid == 0) {
        int o = 0;
        for (int i = 0; i < NEXP; i++) { g_off[i] = o; cur[i] = o; o += cnt[i]; }
        g_off[NEXP] = o;
    }
    __syncthreads();
    int pos = atomicAdd(&cur[n], 1);
    g_perm[pos] = tid;
}

// ============================================================================
// Generic dense SGEMM: C[M,N] = A[M,K](lda) @ W[K,N](ldw) + bias
// BM=BN=BK=32, 256 threads, 2x2 thread tile. Grid (N/32, M/32).
// ============================================================================
__global__ void __launch_bounds__(256) sgemm_bias_k(
    const float* __restrict__ A, int lda,
    const float* __restrict__ W, int ldw,
    const float* __restrict__ bias,
    float* __restrict__ C, int ldc, int K)
{
    __shared__ float As[32][34];   // [k][m], padded
    __shared__ float Ws[32][32];   // [k][n]
    int tid = threadIdx.x;
    int tx = tid & 15, ty = tid >> 4;
    int m0 = blockIdx.y * 32, n0 = blockIdx.x * 32;
    int lr = tid >> 3;            // 0..31
    int lq = (tid & 7) * 4;       // 0..28 step 4

    float a00 = 0.f, a01 = 0.f, a10 = 0.f, a11 = 0.f;
    for (int k0 = 0; k0 < K; k0 += 32) {
        float4 a = *(const float4*)(A + (size_t)(m0 + lr) * lda + k0 + lq);
        As[lq + 0][lr] = a.x; As[lq + 1][lr] = a.y;
        As[lq + 2][lr] = a.z; As[lq + 3][lr] = a.w;
        float4 w = *(const float4*)(W + (size_t)(k0 + lr) * ldw + n0 + lq);
        *(float4*)&Ws[lr][lq] = w;
        __syncthreads();
        #pragma unroll
        for (int kk = 0; kk < 32; kk++) {
            float2 av = *(const float2*)&As[kk][ty * 2];
            float2 wv = *(const float2*)&Ws[kk][tx * 2];
            a00 += av.x * wv.x; a01 += av.x * wv.y;
            a10 += av.y * wv.x; a11 += av.y * wv.y;
        }
        __syncthreads();
    }
    int m = m0 + ty * 2, n = n0 + tx * 2;
    float b0 = bias[n], b1 = bias[n + 1];
    C[(size_t)m * ldc + n]       = a00 + b0;
    C[(size_t)m * ldc + n + 1]   = a01 + b1;
    C[(size_t)(m + 1) * ldc + n]     = a10 + b0;
    C[(size_t)(m + 1) * ldc + n + 1] = a11 + b1;
}

// ============================================================================
// Expert-grouped GEMM: for each expert e, rows {b : D[b]==e} of bert @ spec_W[e]
// Grid (H/32, NEXP). Same tiling as dense GEMM, A rows gathered via g_perm.
// ============================================================================
__global__ void __launch_bounds__(256) sgemm_expert_k(
    const float* __restrict__ bert,
    const float* __restrict__ spec_W,
    const float* __restrict__ spec_b,
    float* __restrict__ C)   // [B,H]
{
    int e = blockIdx.y;
    int n0 = blockIdx.x * 32;
    int start = g_off[e];
    int cnt = g_off[e + 1] - start;
    if (cnt == 0) return;
    const float* W = spec_W + (size_t)e * E_ * H_;

    __shared__ float As[32][34];
    __shared__ float Ws[32][32];
    int tid = threadIdx.x;
    int tx = tid & 15, ty = tid >> 4;
    int lr = tid >> 3;
    int lq = (tid & 7) * 4;

    for (int rb = 0; rb < cnt; rb += 32) {
        int gr = (rb + lr < cnt) ? g_perm[start + rb + lr] : -1;
        float a00 = 0.f, a01 = 0.f, a10 = 0.f, a11 = 0.f;
        for (int k0 = 0; k0 < E_; k0 += 32) {
            float4 a = make_float4(0.f, 0.f, 0.f, 0.f);
            if (gr >= 0)
                a = *(const float4*)(bert + (size_t)gr * E_ + k0 + lq);
            As[lq + 0][lr] = a.x; As[lq + 1][lr] = a.y;
            As[lq + 2][lr] = a.z; As[lq + 3][lr] = a.w;
            float4 w = *(const float4*)(W + (size_t)(k0 + lr) * H_ + n0 + lq);
            *(float4*)&Ws[lr][lq] = w;
            __syncthreads();
            #pragma unroll
            for (int kk = 0; kk < 32; kk++) {
                float2 av = *(const float2*)&As[kk][ty * 2];
                float2 wv = *(const float2*)&Ws[kk][tx * 2];
                a00 += av.x * wv.x; a01 += av.x * wv.y;
                a10 += av.y * wv.x; a11 += av.y * wv.y;
            }
            __syncthreads();
        }
        int n = n0 + tx * 2;
        float b0 = spec_b[e * H_ + n], b1 = spec_b[e * H_ + n + 1];
        int r0 = rb + ty * 2;
        if (r0 < cnt) {
            int gb = g_perm[start + r0];
            C[(size_t)gb * H_ + n]     = a00 + b0;
            C[(size_t)gb * H_ + n + 1] = a01 + b1;
        }
        if (r0 + 1 < cnt) {
            int gb = g_perm[start + r0 + 1];
            C[(size_t)gb * H_ + n]     = a10 + b0;
            C[(size_t)gb * H_ + n + 1] = a11 + b1;
        }
        __syncthreads();
    }
}

// ============================================================================
// LeakyReLU + LayerNorm over a row (n = 384 or 768). 128 threads/row.
// Optional per-row expert-indexed gamma/beta (Didx != nullptr).
// ============================================================================
__global__ void __launch_bounds__(128) leaky_ln_k(
    const float* __restrict__ src, int srcLd,
    float* __restrict__ dst, int dstLd,
    const float* __restrict__ g, const float* __restrict__ be,
    const int* __restrict__ Didx, int n)
{
    int row = blockIdx.x, tid = threadIdx.x;
    int lane = tid & 31, warp = tid >> 5;
    int vpt = n >> 7;            // n/128 (3 or 6)
    const float* s = src + (size_t)row * srcLd;

    float x[6];
    float sum = 0.f;
    for (int i = 0; i < vpt; i++) {
        float v = s[tid + 128 * i];
        v = v > 0.f ? v : LEAKY * v;
        x[i] = v;
        sum += v;
    }

    __shared__ float red[4];
    sum = warpAllSum(sum);
    if (lane == 0) red[warp] = sum;
    __syncthreads();
    float total = red[0] + red[1] + red[2] + red[3];
    float mean = total / (float)n;

    float sq = 0.f;
    for (int i = 0; i < vpt; i++) { float d = x[i] - mean; sq += d * d; }
    __syncthreads();
    sq = warpAllSum(sq);
    if (lane == 0) red[warp] = sq;
    __syncthreads();
    float var = (red[0] + red[1] + red[2] + red[3]) / (float)n;
    float inv = rsqrtf(var + LN_EPS);

    int off = Didx ? Didx[row] * n : 0;
    float* d = dst + (size_t)row * dstLd;
    for (int i = 0; i < vpt; i++) {
        int j = tid + 128 * i;
        d[j] = (x[i] - mean) * inv * g[off + j] + be[off + j];
    }
}

// ============================================================================
// Classifier head: out[b,j] = feat[b,:768] . cls_W[:,j] + cls_b[j], j in {0,1}
// One warp per output. 512 outputs.
// ============================================================================
__global__ void __launch_bounds__(256) cls_k(
    const float* __restrict__ feat, const float* __restrict__ Wc,
    const float* __restrict__ bc, float* __restrict__ out)
{
    int w = (blockIdx.x * blockDim.x + threadIdx.x) >> 5;
    int lane = threadIdx.x & 31;
    int b = w >> 1, j = w & 1;
    float t = 0.f;
    #pragma unroll
    for (int i = 0; i < 24; i++) {
        int e = lane + 32 * i;
        t += feat[(size_t)b * 768 + e] * Wc[e * 2 + j];
    }
    t = warpAllSum(t);
    if (lane == 0) out[b * 2 + j] = t + bc[j];
}

// Domain head: out[b,j] = leaky(d[b]) . dom_W2[:,j] + dom_b2[j], j<9
__global__ void __launch_bounds__(256) dom2_k(
    const float* __restrict__ dvec, const float* __restrict__ W2,
    const float* __restrict__ b2, float* __restrict__ out)
{
    int w = (blockIdx.x * blockDim.x + threadIdx.x) >> 5;
    int lane = threadIdx.x & 31;
    if (w >= B_ * NEXP) return;
    int b = w / NEXP, j = w % NEXP;
    float t = 0.f;
    #pragma unroll
    for (int i = 0; i < 12; i++) {
        int e = lane + 32 * i;
        float v = dvec[(size_t)b * H_ + e];
        v = v > 0.f ? v : LEAKY * v;
        t += v * W2[e * NEXP + j];
    }
    t = warpAllSum(t);
    if (lane == 0) out[b * NEXP + j] = t + b2[j];
}

// ============================================================================
extern "C" void kernel_launch(void* const* d_in, const int* in_sizes, int n_in,
                              void* d_out, int out_size)
{
    const float* input    = (const float*)d_in[0];
    const int*   D        = (const int*)  d_in[1];
    const float* w_att    = (const float*)d_in[2];
    const float* shared_W = (const float*)d_in[3];
    const float* shared_b = (const float*)d_in[4];
    const float* shared_g = (const float*)d_in[5];
    const float* shared_be= (const float*)d_in[6];
    const float* spec_W   = (const float*)d_in[7];
    const float* spec_b   = (const float*)d_in[8];
    const float* spec_g   = (const float*)d_in[9];
    const float* spec_be  = (const float*)d_in[10];
    const float* dec_W1   = (const float*)d_in[11];
    const float* dec_b1   = (const float*)d_in[12];
    const float* dec_g1   = (const float*)d_in[13];
    const float* dec_be1  = (const float*)d_in[14];
    const float* dec_W2   = (const float*)d_in[15];
    const float* dec_b2   = (const float*)d_in[16];
    const float* dec_g2   = (const float*)d_in[17];
    const float* dec_be2  = (const float*)d_in[18];
    const float* cls_W    = (const float*)d_in[19];
    const float* cls_b    = (const float*)d_in[20];
    const float* dom_W1   = (const float*)d_in[21];
    const float* dom_b1   = (const float*)d_in[22];
    const float* dom_g1   = (const float*)d_in[23];
    const float* dom_be1  = (const float*)d_in[24];
    const float* dom_W2   = (const float*)d_in[25];
    const float* dom_b2   = (const float*)d_in[26];

    float* out = (float*)d_out;
    float* out_cls  = out + OUT_CLS_OFF;
    float* out_rec  = out + OUT_REC_OFF;
    float* out_bert = out + OUT_BERT_OFF;
    float* out_dom  = out + OUT_DOM_OFF;

    // device scratch pointers (globals referenced directly by kernels)
    float* pre_sh = nullptr; // unused host-side; kernels use symbols
    (void)pre_sh; (void)n_in; (void)in_sizes; (void)out_size;

    // Resolve device symbol addresses once per launch (cheap, host-side)
    // Kernels reference globals directly; we only need pointers for C args.
    static float* p_pre_sh = nullptr;
    static float* p_pre_sp = nullptr;
    static float* p_feat = nullptr;
    static float* p_pre1 = nullptr;
    static float* p_rec = nullptr;
    static float* p_pre2 = nullptr;
    static float* p_pre_d = nullptr;
    static float* p_dom = nullptr;
    if (!p_pre_sh) {
        cudaGetSymbolAddress((void**)&p_pre_sh, g_pre_sh);
        cudaGetSymbolAddress((void**)&p_pre_sp, g_pre_sp);
        cudaGetSymbolAddress((void**)&p_feat,   g_feat);
        cudaGetSymbolAddress((void**)&p_pre1,   g_pre1);
        cudaGetSymbolAddress((void**)&p_rec,    g_rec);
        cudaGetSymbolAddress((void**)&p_pre2,   g_pre2);
        cudaGetSymbolAddress((void**)&p_pre_d,  g_pre_d);
        cudaGetSymbolAddress((void**)&p_dom,    g_dom);
    }

    // 1-2: attention pooling -> bert_feature (directly into d_out)
    pool_partial_k<<<NPART, 256>>>(input, w_att);
    pool_combine_k<<<B_, 256>>>(out_bert);

    // 3: expert grouping
    perm_k<<<1, 256>>>(D);

    // 4: shared branch GEMM  [256,768]x[768,384]
    sgemm_bias_k<<<dim3(H_/32, B_/32), 256>>>(out_bert, E_, shared_W, H_,
                                              shared_b, p_pre_sh, H_, E_);
    // 5: specific branch (expert-grouped)
    sgemm_expert_k<<<dim3(H_/32, NEXP), 256>>>(out_bert, spec_W, spec_b, p_pre_sp);

    // 6-7: LeakyReLU+LN into feature[:, :384] and [:, 384:]
    leaky_ln_k<<<B_, 128>>>(p_pre_sh, H_, p_feat, 2*H_, shared_g, shared_be, nullptr, H_);
    leaky_ln_k<<<B_, 128>>>(p_pre_sp, H_, p_feat + H_, 2*H_, spec_g, spec_be, D, H_);

    // 8-9: decoder layer 1  [256,768]x[768,384] -> rec
    sgemm_bias_k<<<dim3(H_/32, B_/32), 256>>>(p_feat, 2*H_, dec_W1, H_,
                                              dec_b1, p_pre1, H_, 2*H_);
    leaky_ln_k<<<B_, 128>>>(p_pre1, H_, p_rec, H_, dec_g1, dec_be1, nullptr, H_);

    // 10-11: decoder layer 2  [256,384]x[384,768] -> rec_feature (d_out)
    sgemm_bias_k<<<dim3(E_/32, B_/32), 256>>>(p_rec, H_, dec_W2, E_,
                                              dec_b2, p_pre2, E_, H_);
    leaky_ln_k<<<B_, 128>>>(p_pre2, E_, out_rec, E_, dec_g2, dec_be2, nullptr, E_);

    // 12: classifier head
    cls_k<<<(B_*2*32)/256, 256>>>(p_feat, cls_W, cls_b, out_cls);

    // 13-14: domain layer 1 (input = shared_feature = feat[:, :384], lda=768)
    sgemm_bias_k<<<dim3(H_/32, B_/32), 256>>>(p_feat, 2*H_, dom_W1, H_,
                                              dom_b1, p_pre_d, H_, H_);
    leaky_ln_k<<<B_, 128>>>(p_pre_d, H_, p_dom, H_, dom_g1, dom_be1, nullptr, H_);

    // 15: domain head
    dom2_k<<<(B_*NEXP*32 + 255)/256, 256>>>(p_dom, dom_W2, dom_b2, out_dom);
}

// round 2
// speedup vs baseline: 1.2629x; 1.2629x over previous
#include <cuda_runtime.h>
#include <cuda_bf16.h>
#include <cstdint>

// Problem constants
#define B_   256
#define L_   512
#define E_   768
#define H_   384
#define NEXP 9

#define LEAKY 0.01f
#define LN_EPS 1e-5f

// Output layout: output[B,2], rec_feature[B,E], bert_feature[B,E], domain_pred[B,N]
#define OUT_CLS_OFF  0
#define OUT_REC_OFF  (B_*2)
#define OUT_BERT_OFF (B_*2 + B_*E_)
#define OUT_DOM_OFF  (B_*2 + 2*B_*E_)

// -------- device scratch --------
#define NPART 2048
#define PART_STRIDE 772
__device__ float g_partial[NPART * PART_STRIDE];
__device__ float g_partA[8 * B_ * H_];     // 786432 floats (== 4*B*E too)
__device__ float g_partB[4 * B_ * H_];
__device__ float g_feat[B_ * 2 * H_];
__device__ float g_rec[B_ * H_];
__device__ float g_dom[B_ * H_];
__device__ int   g_perm[B_];
__device__ int   g_off[NEXP + 1];

__device__ __forceinline__ float warpAllSum(float v) {
    #pragma unroll
    for (int o = 16; o > 0; o >>= 1) v += __shfl_xor_sync(0xffffffffu, v, o);
    return v;
}

// ============================================================================
// Kernel 1: single-pass attention pooling partials (unchanged — near HBM bound)
// ============================================================================
__global__ void __launch_bounds__(256) pool_partial_k(
    const float* __restrict__ input, const float* __restrict__ w_att)
{
    int bx = blockIdx.x;
    int b = bx >> 3, chunk = bx & 7;
    int tid = threadIdx.x, lane = tid & 31, warp = tid >> 5;

    const float* base = input + ((size_t)(b * L_ + chunk * 64 + warp * 8)) * E_;

    float4 wr[6];
    #pragma unroll
    for (int k = 0; k < 6; k++)
        wr[k] = *(const float4*)(w_att + 4 * lane + 128 * k);

    float4 acc[6];
    #pragma unroll
    for (int k = 0; k < 6; k++) acc[k] = make_float4(0.f, 0.f, 0.f, 0.f);
    float m = -1e30f, s = 0.f;

    #pragma unroll
    for (int r = 0; r < 8; r++) {
        const float* row = base + (size_t)r * E_;
        float4 v[6];
        #pragma unroll
        for (int k = 0; k < 6; k++)
            v[k] = *(const float4*)(row + 4 * lane + 128 * k);

        float dot = 0.f;
        #pragma unroll
        for (int k = 0; k < 6; k++)
            dot += v[k].x * wr[k].x + v[k].y * wr[k].y + v[k].z * wr[k].z + v[k].w * wr[k].w;
        dot = warpAllSum(dot);

        float mn = fmaxf(m, dot);
        float sc = __expf(m - mn);
        float w  = __expf(dot - mn);
        s = s * sc + w;
        #pragma unroll
        for (int k = 0; k < 6; k++) {
            acc[k].x = acc[k].x * sc + w * v[k].x;
            acc[k].y = acc[k].y * sc + w * v[k].y;
            acc[k].z = acc[k].z * sc + w * v[k].z;
            acc[k].w = acc[k].w * sc + w * v[k].w;
        }
        m = mn;
    }

    __shared__ float sm_m[8], sm_s[8];
    __shared__ float sm_acc[8][E_];
    __shared__ float sM, sc8[8];

    if (lane == 0) { sm_m[warp] = m; sm_s[warp] = s; }
    #pragma unroll
    for (int k = 0; k < 6; k++)
        *(float4*)&sm_acc[warp][4 * lane + 128 * k] = acc[k];
    __syncthreads();

    if (tid == 0) {
        float M = sm_m[0];
        #pragma unroll
        for (int w = 1; w < 8; w++) M = fmaxf(M, sm_m[w]);
        sM = M;
    }
    __syncthreads();
    if (tid < 8) sc8[tid] = __expf(sm_m[tid] - sM);
    __syncthreads();

    float* out = g_partial + (size_t)bx * PART_STRIDE;
    if (tid == 0) {
        float S = 0.f;
        #pragma unroll
        for (int w = 0; w < 8; w++) S += sc8[w] * sm_s[w];
        out[0] = sM; out[1] = S;
    }
    #pragma unroll
    for (int i = 0; i < 3; i++) {
        int e = tid + 256 * i;
        float t = 0.f;
        #pragma unroll
        for (int w = 0; w < 8; w++) t += sc8[w] * sm_acc[w][e];
        out[4 + e] = t;
    }
}

__global__ void __launch_bounds__(256) pool_combine_k(float* __restrict__ bert)
{
    int b = blockIdx.x, tid = threadIdx.x;
    float mc[8];
    float M = -1e30f;
    #pragma unroll
    for (int c = 0; c < 8; c++) {
        mc[c] = g_partial[(size_t)(b * 8 + c) * PART_STRIDE];
        M = fmaxf(M, mc[c]);
    }
    float sc[8], S = 0.f;
    #pragma unroll
    for (int c = 0; c < 8; c++) {
        sc[c] = __expf(mc[c] - M);
        S += sc[c] * g_partial[(size_t)(b * 8 + c) * PART_STRIDE + 1];
    }
    float invS = 1.f / S;
    #pragma unroll
    for (int i = 0; i < 3; i++) {
        int e = tid + 256 * i;
        float t = 0.f;
        #pragma unroll
        for (int c = 0; c < 8; c++)
            t += sc[c] * g_partial[(size_t)(b * 8 + c) * PART_STRIDE + 4 + e];
        bert[(size_t)b * E_ + e] = t * invS;
    }
}

// ============================================================================
// Expert grouping
// ============================================================================
__global__ void perm_k(const int* __restrict__ D)
{
    __shared__ int cnt[NEXP];
    __shared__ int cur[NEXP];
    int tid = threadIdx.x;
    if (tid < NEXP) cnt[tid] = 0;
    __syncthreads();
    int n = D[tid];
    atomicAdd(&cnt[n], 1);
    __syncthreads();
    if (tid == 0) {
        int o = 0;
        for (int i = 0; i < NEXP; i++) { g_off[i] = o; cur[i] = o; o += cnt[i]; }
        g_off[NEXP] = o;
    }
    __syncthreads();
    int pos = atomicAdd(&cur[n], 1);
    g_perm[pos] = tid;
}

// ============================================================================
// Split-K partial SGEMM: P[z][M][N] += A[M,K_chunk] @ W[K_chunk,N]
// BM=64 BN=64 BK=16, 256 threads, 4x4 thread tile. grid (N/64, M/64, S).
// ============================================================================
__global__ void __launch_bounds__(256) sgemm_part_k(
    const float* __restrict__ A, int lda,
    const float* __restrict__ W, int ldw,
    float* __restrict__ P, int N, int kLen, int partStride)
{
    __shared__ float As[16][68];   // [k][m], 272B stride (16B aligned)
    __shared__ float Bs[16][64];   // [k][n]
    int tid = threadIdx.x;
    int tx = tid & 15, ty = tid >> 4;
    int n0 = blockIdx.x * 64, m0 = blockIdx.y * 64;
    int k0 = blockIdx.z * kLen;

    int arow = tid >> 2, acg = (tid & 3) * 4;   // A: 64 rows x 16 k
    int brow = tid >> 4, bcol = (tid & 15) * 4; // B: 16 rows x 64 n

    float4 acc0 = {0,0,0,0}, acc1 = {0,0,0,0}, acc2 = {0,0,0,0}, acc3 = {0,0,0,0};

    int nb = kLen >> 4;
    for (int kb = 0; kb < nb; kb++) {
        int kk0 = k0 + kb * 16;
        float4 a = *(const float4*)(A + (size_t)(m0 + arow) * lda + kk0 + acg);
        As[acg + 0][arow] = a.x; As[acg + 1][arow] = a.y;
        As[acg + 2][arow] = a.z; As[acg + 3][arow] = a.w;
        float4 b = *(const float4*)(W + (size_t)(kk0 + brow) * ldw + n0 + bcol);
        *(float4*)&Bs[brow][bcol] = b;
        __syncthreads();
        #pragma unroll
        for (int kk = 0; kk < 16; kk++) {
            float4 av = *(const float4*)&As[kk][ty * 4];
            float4 bv = *(const float4*)&Bs[kk][tx * 4];
            acc0.x += av.x * bv.x; acc0.y += av.x * bv.y; acc0.z += av.x * bv.z; acc0.w += av.x * bv.w;
            acc1.x += av.y * bv.x; acc1.y += av.y * bv.y; acc1.z += av.y * bv.z; acc1.w += av.y * bv.w;
            acc2.x += av.z * bv.x; acc2.y += av.z * bv.y; acc2.z += av.z * bv.z; acc2.w += av.z * bv.w;
            acc3.x += av.w * bv.x; acc3.y += av.w * bv.y; acc3.z += av.w * bv.z; acc3.w += av.w * bv.w;
        }
        __syncthreads();
    }

    float* p = P + (size_t)blockIdx.z * partStride + (size_t)(m0 + ty * 4) * N + n0 + tx * 4;
    *(float4*)(p)             = acc0;
    *(float4*)(p + N)         = acc1;
    *(float4*)(p + 2 * (size_t)N) = acc2;
    *(float4*)(p + 3 * (size_t)N) = acc3;
}

// ============================================================================
// Expert-grouped split-K partial GEMM. BM=32 BN=64 BK=16, thread tile 2x4.
// grid (H/64, NEXP, S). Writes P[z][b][H] at global sample rows.
// ============================================================================
__global__ void __launch_bounds__(256) sgemm_expert_part_k(
    const float* __restrict__ bert, const float* __restrict__ spec_W,
    float* __restrict__ P, int kLen, int partStride)
{
    int e = blockIdx.y;
    int start = g_off[e];
    int cnt = g_off[e + 1] - start;
    if (cnt == 0) return;
    int n0 = blockIdx.x * 64;
    int k0 = blockIdx.z * kLen;
    const float* W = spec_W + (size_t)e * E_ * H_;

    __shared__ float As[16][36];
    __shared__ float Bs[16][64];
    int tid = threadIdx.x;
    int tx = tid & 15, ty = tid >> 4;
    int brow = tid >> 4, bcol = (tid & 15) * 4;
    int nb = kLen >> 4;

    for (int rb = 0; rb < cnt; rb += 32) {
        int gr = -1;
        if (tid < 128) {
            int r = rb + (tid >> 2);
            if (r < cnt) gr = g_perm[start + r];
        }
        float4 acc0 = {0,0,0,0}, acc1 = {0,0,0,0};

        for (int kb = 0; kb < nb; kb++) {
            int kk0 = k0 + kb * 16;
            if (tid < 128) {
                int arow = tid >> 2, acg = (tid & 3) * 4;
                float4 a = make_float4(0.f, 0.f, 0.f, 0.f);
                if (gr >= 0)
                    a = *(const float4*)(bert + (size_t)gr * E_ + kk0 + acg);
                As[acg + 0][arow] = a.x; As[acg + 1][arow] = a.y;
                As[acg + 2][arow] = a.z; As[acg + 3][arow] = a.w;
            }
            float4 b = *(const float4*)(W + (size_t)(kk0 + brow) * H_ + n0 + bcol);
            *(float4*)&Bs[brow][bcol] = b;
            __syncthreads();
            #pragma unroll
            for (int kk = 0; kk < 16; kk++) {
                float a0 = As[kk][ty * 2];
                float a1 = As[kk][ty * 2 + 1];
                float4 bv = *(const float4*)&Bs[kk][tx * 4];
                acc0.x += a0 * bv.x; acc0.y += a0 * bv.y; acc0.z += a0 * bv.z; acc0.w += a0 * bv.w;
                acc1.x += a1 * bv.x; acc1.y += a1 * bv.y; acc1.z += a1 * bv.z; acc1.w += a1 * bv.w;
            }
            __syncthreads();
        }

        int r0 = rb + ty * 2;
        float* pz = P + (size_t)blockIdx.z * partStride;
        if (r0 < cnt) {
            int gb = g_perm[start + r0];
            *(float4*)(pz + (size_t)gb * H_ + n0 + tx * 4) = acc0;
        }
        if (r0 + 1 < cnt) {
            int gb = g_perm[start + r0 + 1];
            *(float4*)(pz + (size_t)gb * H_ + n0 + tx * 4) = acc1;
        }
        __syncthreads();
    }
}

// ============================================================================
// Fused: sum split-K partials + bias + LeakyReLU + LayerNorm.
// Optional expert-indexed bias/gamma/beta (Didx). 128 threads/row.
// ============================================================================
__global__ void __launch_bounds__(128) reduce_ln_k(
    const float* __restrict__ P, int partStride, int S,
    const float* __restrict__ bias, const float* __restrict__ g,
    const float* __restrict__ be, const int* __restrict__ Didx,
    float* __restrict__ dst, int dstLd, int n)
{
    int row = blockIdx.x, tid = threadIdx.x;
    int lane = tid & 31, warp = tid >> 5;
    int vpt = n >> 7;
    int off = Didx ? Didx[row] * n : 0;

    float x[6];
    float sum = 0.f;
    for (int i = 0; i < vpt; i++) {
        int j = tid + 128 * i;
        float v = bias[off + j];
        for (int s = 0; s < S; s++)
            v += P[(size_t)s * partStride + (size_t)row * n + j];
        v = v > 0.f ? v : LEAKY * v;
        x[i] = v;
        sum += v;
    }

    __shared__ float red[4];
    sum = warpAllSum(sum);
    if (lane == 0) red[warp] = sum;
    __syncthreads();
    float mean = (red[0] + red[1] + red[2] + red[3]) / (float)n;

    float sq = 0.f;
    for (int i = 0; i < vpt; i++) { float d = x[i] - mean; sq += d * d; }
    __syncthreads();
    sq = warpAllSum(sq);
    if (lane == 0) red[warp] = sq;
    __syncthreads();
    float var = (red[0] + red[1] + red[2] + red[3]) / (float)n;
    float inv = rsqrtf(var + LN_EPS);

    float* d = dst + (size_t)row * dstLd;
    for (int i = 0; i < vpt; i++) {
        int j = tid + 128 * i;
        d[j] = (x[i] - mean) * inv * g[off + j] + be[off + j];
    }
}

// ============================================================================
// Tiny heads
// ============================================================================
__global__ void __launch_bounds__(256) cls_k(
    const float* __restrict__ feat, const float* __restrict__ Wc,
    const float* __restrict__ bc, float* __restrict__ out)
{
    int w = (blockIdx.x * blockDim.x + threadIdx.x) >> 5;
    int lane = threadIdx.x & 31;
    int b = w >> 1, j = w & 1;
    float t = 0.f;
    #pragma unroll
    for (int i = 0; i < 24; i++) {
        int e = lane + 32 * i;
        t += feat[(size_t)b * 768 + e] * Wc[e * 2 + j];
    }
    t = warpAllSum(t);
    if (lane == 0) out[b * 2 + j] = t + bc[j];
}

__global__ void __launch_bounds__(256) dom2_k(
    const float* __restrict__ dvec, const float* __restrict__ W2,
    const float* __restrict__ b2, float* __restrict__ out)
{
    int w = (blockIdx.x * blockDim.x + threadIdx.x) >> 5;
    int lane = threadIdx.x & 31;
    if (w >= B_ * NEXP) return;
    int b = w / NEXP, j = w % NEXP;
    float t = 0.f;
    #pragma unroll
    for (int i = 0; i < 12; i++) {
        int e = lane + 32 * i;
        float v = dvec[(size_t)b * H_ + e];
        v = v > 0.f ? v : LEAKY * v;
        t += v * W2[e * NEXP + j];
    }
    t = warpAllSum(t);
    if (lane == 0) out[b * NEXP + j] = t + b2[j];
}

// ============================================================================
extern "C" void kernel_launch(void* const* d_in, const int* in_sizes, int n_in,
                              void* d_out, int out_size)
{
    const float* input    = (const float*)d_in[0];
    const int*   D        = (const int*)  d_in[1];
    const float* w_att    = (const float*)d_in[2];
    const float* shared_W = (const float*)d_in[3];
    const float* shared_b = (const float*)d_in[4];
    const float* shared_g = (const float*)d_in[5];
    const float* shared_be= (const float*)d_in[6];
    const float* spec_W   = (const float*)d_in[7];
    const float* spec_b   = (const float*)d_in[8];
    const float* spec_g   = (const float*)d_in[9];
    const float* spec_be  = (const float*)d_in[10];
    const float* dec_W1   = (const float*)d_in[11];
    const float* dec_b1   = (const float*)d_in[12];
    const float* dec_g1   = (const float*)d_in[13];
    const float* dec_be1  = (const float*)d_in[14];
    const float* dec_W2   = (const float*)d_in[15];
    const float* dec_b2   = (const float*)d_in[16];
    const float* dec_g2   = (const float*)d_in[17];
    const float* dec_be2  = (const float*)d_in[18];
    const float* cls_W    = (const float*)d_in[19];
    const float* cls_b    = (const float*)d_in[20];
    const float* dom_W1   = (const float*)d_in[21];
    const float* dom_b1   = (const float*)d_in[22];
    const float* dom_g1   = (const float*)d_in[23];
    const float* dom_be1  = (const float*)d_in[24];
    const float* dom_W2   = (const float*)d_in[25];
    const float* dom_b2   = (const float*)d_in[26];
    (void)n_in; (void)in_sizes; (void)out_size;

    float* out = (float*)d_out;
    float* out_cls  = out + OUT_CLS_OFF;
    float* out_rec  = out + OUT_REC_OFF;
    float* out_bert = out + OUT_BERT_OFF;
    float* out_dom  = out + OUT_DOM_OFF;

    static float* pA = nullptr;
    static float* pB = nullptr;
    static float* p_feat = nullptr;
    static float* p_rec = nullptr;
    static float* p_dom = nullptr;
    if (!pA) {
        cudaGetSymbolAddress((void**)&pA,     g_partA);
        cudaGetSymbolAddress((void**)&pB,     g_partB);
        cudaGetSymbolAddress((void**)&p_feat, g_feat);
        cudaGetSymbolAddress((void**)&p_rec,  g_rec);
        cudaGetSymbolAddress((void**)&p_dom,  g_dom);
    }

    const int psH = B_ * H_;   // 98304
    const int psE = B_ * E_;   // 196608

    // 1-2: attention pooling -> bert_feature (d_out)
    pool_partial_k<<<NPART, 256>>>(input, w_att);
    pool_combine_k<<<B_, 256>>>(out_bert);

    // 3: expert grouping
    perm_k<<<1, 256>>>(D);

    // 4: shared GEMM partial [256,768]x[768,384], S=8
    sgemm_part_k<<<dim3(H_/64, B_/64, 8), 256>>>(out_bert, E_, shared_W, H_,
                                                 pA, H_, 96, psH);
    // 5: expert GEMM partial, S=4
    sgemm_expert_part_k<<<dim3(H_/64, NEXP, 4), 256>>>(out_bert, spec_W, pB, 192, psH);

    // 6-7: fused reduce+bias+leaky+LN -> feature
    reduce_ln_k<<<B_, 128>>>(pA, psH, 8, shared_b, shared_g, shared_be, nullptr,
                             p_feat, 2*H_, H_);
    reduce_ln_k<<<B_, 128>>>(pB, psH, 4, spec_b, spec_g, spec_be, D,
                             p_feat + H_, 2*H_, H_);

    // 8: decoder layer 1 [256,768]x[768,384], S=8
    sgemm_part_k<<<dim3(H_/64, B_/64, 8), 256>>>(p_feat, 2*H_, dec_W1, H_,
                                                 pA, H_, 96, psH);
    reduce_ln_k<<<B_, 128>>>(pA, psH, 8, dec_b1, dec_g1, dec_be1, nullptr,
                             p_rec, H_, H_);

    // 9: decoder layer 2 [256,384]x[384,768], S=4
    sgemm_part_k<<<dim3(E_/64, B_/64, 4), 256>>>(p_rec, H_, dec_W2, E_,
                                                 pA, E_, 96, psE);
    reduce_ln_k<<<B_, 128>>>(pA, psE, 4, dec_b2, dec_g2, dec_be2, nullptr,
                             out_rec, E_, E_);

    // 10: classifier head
    cls_k<<<(B_*2*32)/256, 256>>>(p_feat, cls_W, cls_b, out_cls);

    // 11: domain layer 1 [256,384]x[384,384], S=8 (uses feat[:, :384])
    sgemm_part_k<<<dim3(H_/64, B_/64, 8), 256>>>(p_feat, 2*H_, dom_W1, H_,
                                                 pA, H_, 48, psH);
    reduce_ln_k<<<B_, 128>>>(pA, psH, 8, dom_b1, dom_g1, dom_be1, nullptr,
                             p_dom, H_, H_);

    // 12: domain head
    dom2_k<<<(B_*NEXP*32 + 255)/256, 256>>>(p_dom, dom_W2, dom_b2, out_dom);
}